// round 7
// baseline (speedup 1.0000x reference)
#include <cuda_runtime.h>

#define CUT2 25.0f
#define IT 4            // i-rows per group (register tile)
#define NROWS_CAP 65536
#define NGRP_CAP  (NROWS_CAP / IT)
#define MAXCH 32        // max 32-wide j-chunks per row (nat <= 1024)
#define NSYS_CAP 2048

// Scratch (static __device__, allocation-free).
__device__ uint4 g_mask[NGRP_CAP * MAXCH];  // [group][chunk] -> 4 rows' ballots
__device__ int   g_offsets[NROWS_CAP];      // within-system exclusive prefix
__device__ int   g_systot[NSYS_CAP];        // per-system totals

// ---- bit-exact reference arithmetic (DO NOT CHANGE) ----
__device__ __forceinline__ float sqnorm3(float x, float y, float z) {
    return __fadd_rn(__fadd_rn(__fmul_rn(x, x), __fmul_rn(y, y)), __fmul_rn(z, z));
}
// gram dot via GEMM-style FMA chain: c = rn(x*x'); c = fma(y,y',c); c = fma(z,z',c)
__device__ __forceinline__ float dot3(float4 a, float4 b) {
    return __fmaf_rn(a.z, b.z, __fmaf_rn(a.y, b.y, __fmul_rn(a.x, b.x)));
}
__device__ __forceinline__ float d12_of(float4 ai, float4 aj) {
    return __fsub_rn(__fadd_rn(ai.w, aj.w), __fmul_rn(2.0f, dot3(ai, aj)));
}
// Doubled-operand form: ajd = (2x', 2y', 2z', sq'). The same FMA chain on the
// doubled operand returns exactly 2*dot3 (rn(2a) == 2*rn(a): scaling by a
// power of two commutes with round-to-nearest; no overflow at these ranges),
// so d12_of_dbl(ai, ajd) == d12_of(ai, aj) bit-for-bit, one FMUL cheaper.
__device__ __forceinline__ float d12_of_dbl(float4 ai, float4 ajd) {
    float g2 = __fmaf_rn(ai.z, ajd.z, __fmaf_rn(ai.y, ajd.y,
                         __fmul_rn(ai.x, ajd.x)));
    return __fsub_rn(__fadd_rn(ai.w, ajd.w), g2);
}
// --------------------------------------------------------

extern __shared__ float4 s_dyn[];

// K1: mask sweep. Warp handles IT consecutive rows; per 32-j chunk emits one
// uint4 of ballots. smem holds (2x, 2y, 2z, sq); sentinel tail kills j >= nat.
__global__ void sweep_kernel(const float* __restrict__ coords, int nat,
                             int nch, int ngroups) {
    float4* s_at = s_dyn;
    int s = blockIdx.x;
    {
        const float* base = coords + (size_t)s * nat * 3;
        int P = nch * 32;
        for (int t = threadIdx.x; t < P; t += blockDim.x) {
            if (t < nat) {
                float x = base[3 * t + 0];
                float y = base[3 * t + 1];
                float z = base[3 * t + 2];
                s_at[t] = make_float4(2.0f * x, 2.0f * y, 2.0f * z,
                                      sqnorm3(x, y, z));
            } else {
                s_at[t] = make_float4(0.f, 0.f, 0.f, 1e30f);  // never a hit
            }
        }
        __syncthreads();
    }

    int lane = threadIdx.x & 31;
    int wid  = (threadIdx.x >> 5) + blockIdx.y * (blockDim.x >> 5);
    int wtot = (blockDim.x >> 5) * gridDim.y;

    // Zigzag group assignment balances triangular work across warps.
    for (int base = 0; base * wtot < ngroups; base++) {
        int g = (base & 1) ? ((base + 1) * wtot - 1 - wid) : (base * wtot + wid);
        if (g >= ngroups) continue;

        int r0 = g * IT;
        float4 a[IT];
#pragma unroll
        for (int t = 0; t < IT; t++) {
            int i = r0 + t;
            if (i < nat) {
                float4 v = s_at[i];
                a[t] = make_float4(0.5f * v.x, 0.5f * v.y, 0.5f * v.z, v.w);
            } else {
                a[t] = make_float4(0.f, 0.f, 0.f, 1e30f);
            }
        }

        uint4* mp = &g_mask[(size_t)(s * ngroups + g) * nch];
        int c0 = (r0 + 1) >> 5;  // first chunk containing any j > r0

        // Peeled first chunk: needs the j > i predicate.
        int c = c0;
        if (c < nch) {
            int j = (c << 5) + lane;
            float4 aj = s_at[j];
            unsigned m0 = __ballot_sync(0xffffffffu,
                (d12_of_dbl(a[0], aj) < CUT2) && (j > r0));
            unsigned m1 = __ballot_sync(0xffffffffu,
                (d12_of_dbl(a[1], aj) < CUT2) && (j > r0 + 1));
            unsigned m2 = __ballot_sync(0xffffffffu,
                (d12_of_dbl(a[2], aj) < CUT2) && (j > r0 + 2));
            unsigned m3 = __ballot_sync(0xffffffffu,
                (d12_of_dbl(a[3], aj) < CUT2) && (j > r0 + 3));
            if (lane == 0) mp[c] = make_uint4(m0, m1, m2, m3);
            c++;
        }

        // Clean chunks: j > i guaranteed; sentinels kill j >= nat.
        for (; c < nch; c++) {
            int j = (c << 5) + lane;
            float4 aj = s_at[j];
            unsigned m0 = __ballot_sync(0xffffffffu, d12_of_dbl(a[0], aj) < CUT2);
            unsigned m1 = __ballot_sync(0xffffffffu, d12_of_dbl(a[1], aj) < CUT2);
            unsigned m2 = __ballot_sync(0xffffffffu, d12_of_dbl(a[2], aj) < CUT2);
            unsigned m3 = __ballot_sync(0xffffffffu, d12_of_dbl(a[3], aj) < CUT2);
            if (lane == 0) mp[c] = make_uint4(m0, m1, m2, m3);
        }
    }
}

// K2: per-system exclusive scan; counts derived from masks.
// grid = nsys, block = 1024 (requires nat <= 1024).
__global__ void scan_sys_kernel(int nat, int nch, int ngroups) {
    __shared__ int wsum[32];
    int s = blockIdx.x;
    int tid = threadIdx.x;
    int lane = tid & 31, w = tid >> 5;

    int v = 0;
    if (tid < nat) {
        int g = tid >> 2, t = tid & 3;
        int c0 = ((g << 2) + 1) >> 5;
        const unsigned* mp =
            (const unsigned*)&g_mask[(size_t)(s * ngroups + g) * nch];
        for (int c = c0; c < nch; c++) v += __popc(mp[(c << 2) + t]);
    }

    int x = v;
#pragma unroll
    for (int o = 1; o < 32; o <<= 1) {
        int u = __shfl_up_sync(0xffffffffu, x, o);
        if (lane >= o) x += u;
    }
    if (lane == 31) wsum[w] = x;
    __syncthreads();
    if (w == 0) {
        int y = wsum[lane];
#pragma unroll
        for (int o = 1; o < 32; o <<= 1) {
            int u = __shfl_up_sync(0xffffffffu, y, o);
            if (lane >= o) y += u;
        }
        wsum[lane] = y;
    }
    __syncthreads();
    int incl = x + ((w > 0) ? wsum[w - 1] : 0);
    if (tid < nat) g_offsets[s * nat + tid] = incl - v;
    if (tid == nat - 1) g_systot[s] = incl;
}

// K3: fused output, 1024-thread blocks. Blocks [0, WB): system-slab duty —
// block handles 32 rows of ONE system, caching that system's atoms
// (x, y, z, sq) in smem; lane c owns chunk c; shfl-scan of popcounts gives
// each hit its exact j-ascending position; d12 recomputed bit-exactly from
// the cached atoms. Blocks [WB, ...): padding region (concurrent, disjoint).
// Output float32 layout (maxp = MAX_PAIRS):
//   [0,M): src   [M,2M): dst    (edge_src = concat(src,dst))
//   [2M,3M): dst [3M,4M): src   (edge_dst = concat(dst,src))
//   [4M,5M): d12 [5M,6M): d12   [6M]: npairs
__global__ void output_kernel(const float* __restrict__ coords,
                              float* __restrict__ out, int maxp,
                              int nat, int nsys, int nch, int ngroups,
                              int nwb, int WB, float padval, int vec_ok) {
    __shared__ int s_sysoff[NSYS_CAP + 1];
    float4* s_atoms = s_dyn;
    int tid = threadIdx.x;
    bool is_write = (blockIdx.x < WB);
    int s = is_write ? (int)(blockIdx.x / nwb) : 0;

    if (is_write) {
        const float* base = coords + (size_t)s * nat * 3;
        for (int t = tid; t < nat; t += blockDim.x) {
            float x = base[3 * t + 0];
            float y = base[3 * t + 1];
            float z = base[3 * t + 2];
            s_atoms[t] = make_float4(x, y, z, sqnorm3(x, y, z));
        }
    }
    if (tid < 32) {
        int per = (nsys + 31) >> 5;
        int bbase = tid * per;
        int loc[8];
        int sum = 0;
        for (int u = 0; u < per && u < 8; u++) {
            int idx = bbase + u;
            int t = (idx < nsys) ? g_systot[idx] : 0;
            loc[u] = sum;
            sum += t;
        }
        int x = sum;
#pragma unroll
        for (int o = 1; o < 32; o <<= 1) {
            int uu = __shfl_up_sync(0xffffffffu, x, o);
            if (tid >= o) x += uu;
        }
        int excl = x - sum;
        for (int u = 0; u < per && u < 8; u++) {
            int idx = bbase + u;
            if (idx < nsys) s_sysoff[idx] = excl + loc[u];
        }
        if (tid == 31) s_sysoff[nsys] = x;  // grand total = npairs
    }
    __syncthreads();
    int np = s_sysoff[nsys];

    if (is_write) {
        int wb = blockIdx.x - s * nwb;
        int i = wb * 32 + (tid >> 5);       // row within system
        if (i >= nat) return;
        int lane = tid & 31;
        int row = s * nat + i;
        int g = i >> 2, t = i & 3;
        int c0 = ((g << 2) + 1) >> 5;

        unsigned m = 0;
        if (lane >= c0 && lane < nch)
            m = ((const unsigned*)&g_mask[(size_t)(s * ngroups + g) * nch])
                 [(lane << 2) + t];
        int cnt = __popc(m);

        int x = cnt;  // inclusive scan across lanes (chunks)
#pragma unroll
        for (int o = 1; o < 32; o <<= 1) {
            int u = __shfl_up_sync(0xffffffffu, x, o);
            if (lane >= o) x += u;
        }
        int mybase = x - cnt;

        if (m) {
            float4 ai = s_atoms[i];
            float fsrc = (float)row;
            int off = s_sysoff[s] + g_offsets[row] + mybase;
            float fsysbase = (float)(s * nat);

            int r = 0;
            while (m) {
                int b = __ffs(m) - 1;
                m &= m - 1;
                int j = (lane << 5) + b;
                float4 aj = s_atoms[j];
                float d = d12_of(ai, aj);
                int pos = off + r;
                r++;
                if (pos < maxp) {
                    float fdst = fsysbase + (float)j;
                    out[pos]            = fsrc;
                    out[maxp + pos]     = fdst;
                    out[2 * maxp + pos] = fdst;
                    out[3 * maxp + pos] = fsrc;
                    out[4 * maxp + pos] = d;
                    out[5 * maxp + pos] = d;
                }
            }
        }
    } else {
        int pb = blockIdx.x - WB;
        if (pb == 0 && tid == 0) out[6 * maxp] = (float)np;
        int k0 = (pb * blockDim.x + tid) * 4;
        if (k0 >= maxp) return;
        if (k0 >= np && k0 + 3 < maxp && vec_ok) {
            float4 pv = make_float4(padval, padval, padval, padval);
            float4 cv = make_float4(CUT2, CUT2, CUT2, CUT2);
            *(float4*)(out + k0)            = pv;
            *(float4*)(out + maxp + k0)     = pv;
            *(float4*)(out + 2 * maxp + k0) = pv;
            *(float4*)(out + 3 * maxp + k0) = pv;
            *(float4*)(out + 4 * maxp + k0) = cv;
            *(float4*)(out + 5 * maxp + k0) = cv;
        } else {
#pragma unroll
            for (int u = 0; u < 4; u++) {
                int k = k0 + u;
                if (k < maxp && k >= np) {
                    out[k]            = padval;
                    out[maxp + k]     = padval;
                    out[2 * maxp + k] = padval;
                    out[3 * maxp + k] = padval;
                    out[4 * maxp + k] = CUT2;
                    out[5 * maxp + k] = CUT2;
                }
            }
        }
    }
}

extern "C" void kernel_launch(void* const* d_in, const int* in_sizes, int n_in,
                              void* d_out, int out_size) {
    const float* coords = (const float*)d_in[0];
    int n    = in_sizes[1];          // total atoms
    int nsys = in_sizes[2];          // systems
    int nat  = n / nsys;
    int maxp = (out_size - 1) / 6;   // MAX_PAIRS
    float* out = (float*)d_out;

    int nch = (nat + 31) >> 5;            // 32-wide j-chunks per row (<= 32)
    int ngroups = (nat + IT - 1) / IT;
    size_t smem_sweep = (size_t)nch * 32 * sizeof(float4);
    size_t smem_out   = (size_t)nat * sizeof(float4);
    int vec_ok = ((maxp & 3) == 0) ? 1 : 0;

    int nwb = (nat + 31) / 32;                       // slabs per system
    int WB  = nsys * nwb;                            // write blocks (1024 thr)
    int PB  = (maxp + 1024 * 4 - 1) / (1024 * 4);    // pad blocks

    sweep_kernel<<<dim3(nsys, 16), 256, smem_sweep>>>(coords, nat, nch, ngroups);
    scan_sys_kernel<<<nsys, 1024>>>(nat, nch, ngroups);
    output_kernel<<<WB + PB, 1024, smem_out>>>(coords, out, maxp, nat, nsys,
                                               nch, ngroups, nwb, WB, (float)n,
                                               vec_ok);
}

// round 8
// speedup vs baseline: 1.0877x; 1.0877x over previous
#include <cuda_runtime.h>

#define CUT2 25.0f
#define IT 4            // i-rows per group (register tile)
#define NROWS_CAP 65536
#define NGRP_CAP  (NROWS_CAP / IT)
#define MAXCH 32        // max 32-wide j-chunks per row (nat <= 1024)
#define NSYS_CAP 2048
#define NSYS_SM 257     // smem sysoff capacity (nsys <= 256)

// Scratch (static __device__, allocation-free).
__device__ uint4 g_mask[NGRP_CAP * MAXCH];  // [group][chunk] -> 4 rows' ballots
__device__ int4  g_counts4[NGRP_CAP];       // per-group 4-row hit counts
__device__ int   g_offsets[NROWS_CAP];      // within-system exclusive prefix
__device__ int   g_systot[NSYS_CAP];        // per-system totals

// ---- bit-exact reference arithmetic (DO NOT CHANGE) ----
__device__ __forceinline__ float sqnorm3(float x, float y, float z) {
    return __fadd_rn(__fadd_rn(__fmul_rn(x, x), __fmul_rn(y, y)), __fmul_rn(z, z));
}
// gram dot via GEMM-style FMA chain: c = rn(x*x'); c = fma(y,y',c); c = fma(z,z',c)
__device__ __forceinline__ float dot3(float4 a, float4 b) {
    return __fmaf_rn(a.z, b.z, __fmaf_rn(a.y, b.y, __fmul_rn(a.x, b.x)));
}
__device__ __forceinline__ float d12_of(float4 ai, float4 aj) {
    return __fsub_rn(__fadd_rn(ai.w, aj.w), __fmul_rn(2.0f, dot3(ai, aj)));
}
// Doubled-operand form: ajd = (2x', 2y', 2z', sq'). FMA chain on the doubled
// operand yields exactly 2*dot3 (power-of-two scaling commutes with rn), so
// d12_of_dbl(ai, ajd) == d12_of(ai, aj) bit-for-bit, one FMUL cheaper.
__device__ __forceinline__ float d12_of_dbl(float4 ai, float4 ajd) {
    float g2 = __fmaf_rn(ai.z, ajd.z, __fmaf_rn(ai.y, ajd.y,
                         __fmul_rn(ai.x, ajd.x)));
    return __fsub_rn(__fadd_rn(ai.w, ajd.w), g2);
}
// --------------------------------------------------------

extern __shared__ float4 s_dyn[];

// K1: mask sweep. Warp handles IT consecutive rows; per 32-j chunk emits one
// uint4 of ballots and accumulates per-row counts in registers (stored as an
// int4 per group at the end). smem holds (2x, 2y, 2z, sq); sentinel tail
// kills j >= nat.
__global__ void sweep_kernel(const float* __restrict__ coords, int nat,
                             int nch, int ngroups) {
    float4* s_at = s_dyn;
    int s = blockIdx.x;
    {
        const float* base = coords + (size_t)s * nat * 3;
        int P = nch * 32;
        for (int t = threadIdx.x; t < P; t += blockDim.x) {
            if (t < nat) {
                float x = base[3 * t + 0];
                float y = base[3 * t + 1];
                float z = base[3 * t + 2];
                s_at[t] = make_float4(2.0f * x, 2.0f * y, 2.0f * z,
                                      sqnorm3(x, y, z));
            } else {
                s_at[t] = make_float4(0.f, 0.f, 0.f, 1e30f);  // never a hit
            }
        }
        __syncthreads();
    }

    int lane = threadIdx.x & 31;
    int wid  = (threadIdx.x >> 5) + blockIdx.y * (blockDim.x >> 5);
    int wtot = (blockDim.x >> 5) * gridDim.y;

    // Zigzag group assignment balances triangular work across warps.
    for (int base = 0; base * wtot < ngroups; base++) {
        int g = (base & 1) ? ((base + 1) * wtot - 1 - wid) : (base * wtot + wid);
        if (g >= ngroups) continue;

        int r0 = g * IT;
        float4 a[IT];
#pragma unroll
        for (int t = 0; t < IT; t++) {
            int i = r0 + t;
            if (i < nat) {
                float4 v = s_at[i];
                a[t] = make_float4(0.5f * v.x, 0.5f * v.y, 0.5f * v.z, v.w);
            } else {
                a[t] = make_float4(0.f, 0.f, 0.f, 1e30f);
            }
        }

        uint4* mp = &g_mask[(size_t)(s * ngroups + g) * nch];
        int c0 = (r0 + 1) >> 5;  // first chunk containing any j > r0
        int cnt0 = 0, cnt1 = 0, cnt2 = 0, cnt3 = 0;

        // Peeled first chunk: needs the j > i predicate.
        int c = c0;
        if (c < nch) {
            int j = (c << 5) + lane;
            float4 aj = s_at[j];
            unsigned m0 = __ballot_sync(0xffffffffu,
                (d12_of_dbl(a[0], aj) < CUT2) && (j > r0));
            unsigned m1 = __ballot_sync(0xffffffffu,
                (d12_of_dbl(a[1], aj) < CUT2) && (j > r0 + 1));
            unsigned m2 = __ballot_sync(0xffffffffu,
                (d12_of_dbl(a[2], aj) < CUT2) && (j > r0 + 2));
            unsigned m3 = __ballot_sync(0xffffffffu,
                (d12_of_dbl(a[3], aj) < CUT2) && (j > r0 + 3));
            if (lane == 0) mp[c] = make_uint4(m0, m1, m2, m3);
            cnt0 += __popc(m0); cnt1 += __popc(m1);
            cnt2 += __popc(m2); cnt3 += __popc(m3);
            c++;
        }

        // Clean chunks: j > i guaranteed; sentinels kill j >= nat.
        for (; c < nch; c++) {
            int j = (c << 5) + lane;
            float4 aj = s_at[j];
            unsigned m0 = __ballot_sync(0xffffffffu, d12_of_dbl(a[0], aj) < CUT2);
            unsigned m1 = __ballot_sync(0xffffffffu, d12_of_dbl(a[1], aj) < CUT2);
            unsigned m2 = __ballot_sync(0xffffffffu, d12_of_dbl(a[2], aj) < CUT2);
            unsigned m3 = __ballot_sync(0xffffffffu, d12_of_dbl(a[3], aj) < CUT2);
            if (lane == 0) mp[c] = make_uint4(m0, m1, m2, m3);
            cnt0 += __popc(m0); cnt1 += __popc(m1);
            cnt2 += __popc(m2); cnt3 += __popc(m3);
        }

        if (lane == 0)
            g_counts4[s * ngroups + g] = make_int4(cnt0, cnt1, cnt2, cnt3);
    }
}

// K2: per-system exclusive scan over per-row counts (coalesced int loads).
// grid = nsys, block = 1024 (requires nat <= 1024, nat % 4 == 0 for indexing;
// rows beyond nat have zero counts by construction).
__global__ void scan_sys_kernel(int nat, int ngroups) {
    __shared__ int wsum[32];
    int s = blockIdx.x;
    int tid = threadIdx.x;
    int lane = tid & 31, w = tid >> 5;

    const int* cnts = (const int*)&g_counts4[(size_t)s * ngroups];
    int v = (tid < nat) ? cnts[tid] : 0;

    int x = v;
#pragma unroll
    for (int o = 1; o < 32; o <<= 1) {
        int u = __shfl_up_sync(0xffffffffu, x, o);
        if (lane >= o) x += u;
    }
    if (lane == 31) wsum[w] = x;
    __syncthreads();
    if (w == 0) {
        int y = wsum[lane];
#pragma unroll
        for (int o = 1; o < 32; o <<= 1) {
            int u = __shfl_up_sync(0xffffffffu, y, o);
            if (lane >= o) y += u;
        }
        wsum[lane] = y;
    }
    __syncthreads();
    int incl = x + ((w > 0) ? wsum[w - 1] : 0);
    if (tid < nat) g_offsets[s * nat + tid] = incl - v;
    if (tid == nat - 1) g_systot[s] = incl;
}

// K3: fused output, 256-thr blocks (8 warps). Blocks [0, WB): one warp per
// row; lane c owns chunk c; shfl-scan of popcounts positions each hit in
// exact j-ascending order; d12 recomputed bit-exactly from __ldg coords
// (L2-resident). Blocks [WB, ...): padding region (concurrent, disjoint).
// Output float32 layout (maxp = MAX_PAIRS):
//   [0,M): src   [M,2M): dst    (edge_src = concat(src,dst))
//   [2M,3M): dst [3M,4M): src   (edge_dst = concat(dst,src))
//   [4M,5M): d12 [5M,6M): d12   [6M]: npairs
__global__ void output_kernel(const float* __restrict__ coords,
                              float* __restrict__ out, int maxp, int nrows,
                              int nat, int nsys, int nch, int ngroups,
                              int WB, float padval, int vec_ok) {
    __shared__ int s_sysoff[NSYS_SM];
    int tid = threadIdx.x;
    if (tid < 32) {
        int per = (nsys + 31) >> 5;
        int bbase = tid * per;
        int loc[8];
        int sum = 0;
        for (int u = 0; u < per && u < 8; u++) {
            int idx = bbase + u;
            int t = (idx < nsys) ? g_systot[idx] : 0;
            loc[u] = sum;
            sum += t;
        }
        int x = sum;
#pragma unroll
        for (int o = 1; o < 32; o <<= 1) {
            int uu = __shfl_up_sync(0xffffffffu, x, o);
            if (tid >= o) x += uu;
        }
        int excl = x - sum;
        for (int u = 0; u < per && u < 8; u++) {
            int idx = bbase + u;
            if (idx < nsys && idx < NSYS_SM) s_sysoff[idx] = excl + loc[u];
        }
        if (tid == 31 && nsys < NSYS_SM) s_sysoff[nsys] = x;  // npairs
    }
    __syncthreads();
    int np = s_sysoff[nsys];

    if (blockIdx.x < WB) {
        int row = blockIdx.x * (blockDim.x >> 5) + (tid >> 5);
        if (row >= nrows) return;
        int lane = tid & 31;
        int s = row / nat, i = row - s * nat;
        int g = i >> 2, t = i & 3;
        int c0 = ((g << 2) + 1) >> 5;

        unsigned m = 0;
        if (lane >= c0 && lane < nch)
            m = ((const unsigned*)&g_mask[(size_t)(s * ngroups + g) * nch])
                 [(lane << 2) + t];
        int cnt = __popc(m);

        int x = cnt;  // inclusive scan across lanes (chunks)
#pragma unroll
        for (int o = 1; o < 32; o <<= 1) {
            int u = __shfl_up_sync(0xffffffffu, x, o);
            if (lane >= o) x += u;
        }
        int mybase = x - cnt;

        if (m) {
            const float* ci = coords + (size_t)row * 3;
            float xi = __ldg(ci), yi = __ldg(ci + 1), zi = __ldg(ci + 2);
            float4 ai = make_float4(xi, yi, zi, sqnorm3(xi, yi, zi));
            float fsrc = (float)row;
            float fsysbase = (float)(s * nat);
            int off = s_sysoff[s] + g_offsets[row] + mybase;
            int jb = s * nat + (lane << 5);

            int r = 0;
            while (m) {
                int b = __ffs(m) - 1;
                m &= m - 1;
                int gj = jb + b;
                const float* cj = coords + (size_t)gj * 3;
                float xj = __ldg(cj), yj = __ldg(cj + 1), zj = __ldg(cj + 2);
                float4 aj = make_float4(xj, yj, zj, sqnorm3(xj, yj, zj));
                float d = d12_of(ai, aj);
                int pos = off + r;
                r++;
                if (pos < maxp) {
                    float fdst = fsysbase + (float)(gj - s * nat);
                    out[pos]            = fsrc;
                    out[maxp + pos]     = fdst;
                    out[2 * maxp + pos] = fdst;
                    out[3 * maxp + pos] = fsrc;
                    out[4 * maxp + pos] = d;
                    out[5 * maxp + pos] = d;
                }
            }
        }
    } else {
        int pb = blockIdx.x - WB;
        if (pb == 0 && tid == 0) out[6 * maxp] = (float)np;
        int k0 = (pb * blockDim.x + tid) * 4;
        if (k0 >= maxp) return;
        if (k0 >= np && k0 + 3 < maxp && vec_ok) {
            float4 pv = make_float4(padval, padval, padval, padval);
            float4 cv = make_float4(CUT2, CUT2, CUT2, CUT2);
            *(float4*)(out + k0)            = pv;
            *(float4*)(out + maxp + k0)     = pv;
            *(float4*)(out + 2 * maxp + k0) = pv;
            *(float4*)(out + 3 * maxp + k0) = pv;
            *(float4*)(out + 4 * maxp + k0) = cv;
            *(float4*)(out + 5 * maxp + k0) = cv;
        } else {
#pragma unroll
            for (int u = 0; u < 4; u++) {
                int k = k0 + u;
                if (k < maxp && k >= np) {
                    out[k]            = padval;
                    out[maxp + k]     = padval;
                    out[2 * maxp + k] = padval;
                    out[3 * maxp + k] = padval;
                    out[4 * maxp + k] = CUT2;
                    out[5 * maxp + k] = CUT2;
                }
            }
        }
    }
}

extern "C" void kernel_launch(void* const* d_in, const int* in_sizes, int n_in,
                              void* d_out, int out_size) {
    const float* coords = (const float*)d_in[0];
    int n    = in_sizes[1];          // total atoms
    int nsys = in_sizes[2];          // systems
    int nat  = n / nsys;
    int maxp = (out_size - 1) / 6;   // MAX_PAIRS
    float* out = (float*)d_out;

    int nch = (nat + 31) >> 5;            // 32-wide j-chunks per row (<= 32)
    int ngroups = (nat + IT - 1) / IT;
    size_t smem_sweep = (size_t)nch * 32 * sizeof(float4);
    int vec_ok = ((maxp & 3) == 0) ? 1 : 0;

    int WB = (n + 7) / 8;                          // write blocks (8 warps ea)
    int PB = (maxp + 256 * 4 - 1) / (256 * 4);     // pad blocks

    sweep_kernel<<<dim3(nsys, 16), 256, smem_sweep>>>(coords, nat, nch, ngroups);
    scan_sys_kernel<<<nsys, 1024>>>(nat, ngroups);
    output_kernel<<<WB + PB, 256>>>(coords, out, maxp, n, nat, nsys, nch,
                                    ngroups, WB, (float)n, vec_ok);
}

// round 9
// speedup vs baseline: 1.1847x; 1.0892x over previous
#include <cuda_runtime.h>

#define CUT2 25.0f
#define IT 4            // i-rows per group (register tile)
#define NROWS_CAP 65536
#define NGRP_CAP  (NROWS_CAP / IT)
#define MAXCH 32        // max 32-wide j-chunks per row (nat <= 1024)
#define NSYS_CAP 2048
#define NSYS_SM 257     // smem sysoff capacity (nsys <= 256)

// Scratch (static __device__, allocation-free).
__device__ uint4 g_mask[NGRP_CAP * MAXCH];  // [group][chunk] -> 4 rows' ballots
__device__ int4  g_counts4[NGRP_CAP];       // per-group 4-row hit counts
__device__ int   g_offsets[NROWS_CAP];      // within-system exclusive prefix
__device__ int   g_systot[NSYS_CAP];        // per-system totals

// ---- bit-exact reference arithmetic (DO NOT CHANGE) ----
__device__ __forceinline__ float sqnorm3(float x, float y, float z) {
    return __fadd_rn(__fadd_rn(__fmul_rn(x, x), __fmul_rn(y, y)), __fmul_rn(z, z));
}
// gram dot via GEMM-style FMA chain: c = rn(x*x'); c = fma(y,y',c); c = fma(z,z',c)
__device__ __forceinline__ float dot3(float4 a, float4 b) {
    return __fmaf_rn(a.z, b.z, __fmaf_rn(a.y, b.y, __fmul_rn(a.x, b.x)));
}
__device__ __forceinline__ float d12_of(float4 ai, float4 aj) {
    return __fsub_rn(__fadd_rn(ai.w, aj.w), __fmul_rn(2.0f, dot3(ai, aj)));
}
// --------------------------------------------------------

// ---- packed f32x2 helpers (Blackwell) ----
typedef unsigned long long u64;
__device__ __forceinline__ u64 pack2(float lo, float hi) {
    u64 r; asm("mov.b64 %0, {%1, %2};" : "=l"(r) : "f"(lo), "f"(hi)); return r;
}
__device__ __forceinline__ void unpack2(u64 v, float& lo, float& hi) {
    asm("mov.b64 {%0, %1}, %2;" : "=f"(lo), "=f"(hi) : "l"(v));
}
__device__ __forceinline__ u64 mul2p(u64 a, u64 b) {
    u64 r; asm("mul.rn.f32x2 %0, %1, %2;" : "=l"(r) : "l"(a), "l"(b)); return r;
}
__device__ __forceinline__ u64 add2p(u64 a, u64 b) {
    u64 r; asm("add.rn.f32x2 %0, %1, %2;" : "=l"(r) : "l"(a), "l"(b)); return r;
}
__device__ __forceinline__ u64 fma2p(u64 a, u64 b, u64 c) {
    u64 r; asm("fma.rn.f32x2 %0, %1, %2, %3;" : "=l"(r) : "l"(a), "l"(b), "l"(c));
    return r;
}
// Packed d12 for a row-pair vs one j atom (aj in doubled form (2x,2y,2z,sq)):
//   nax/nay/naz hold (-x_i) per half (exact negation); chain computes -2*dot
//   exactly (rn(-u) = -rn(u), rn(2u) = 2 rn(u)); final add2 = rn(w - 2*dot),
//   bit-identical to the reference d12.
__device__ __forceinline__ u64 d12_pair(u64 nax, u64 nay, u64 naz, u64 aw,
                                        u64 jx, u64 jy, u64 jz, u64 jw) {
    u64 t = mul2p(nax, jx);
    t = fma2p(nay, jy, t);
    t = fma2p(naz, jz, t);
    u64 w = add2p(aw, jw);
    return add2p(w, t);
}
// --------------------------------------------------------

extern __shared__ float4 s_dyn[];

// K1: mask sweep, packed-pair math. Warp handles IT=4 consecutive rows (two
// f32x2 row-pairs); per 32-j chunk emits one uint4 of ballots + accumulates
// counts. smem holds (2x, 2y, 2z, sq); sentinel tail kills j >= nat.
__global__ void sweep_kernel(const float* __restrict__ coords, int nat,
                             int nch, int ngroups) {
    float4* s_at = s_dyn;
    int s = blockIdx.x;
    {
        const float* base = coords + (size_t)s * nat * 3;
        int P = nch * 32;
        for (int t = threadIdx.x; t < P; t += blockDim.x) {
            if (t < nat) {
                float x = base[3 * t + 0];
                float y = base[3 * t + 1];
                float z = base[3 * t + 2];
                s_at[t] = make_float4(2.0f * x, 2.0f * y, 2.0f * z,
                                      sqnorm3(x, y, z));
            } else {
                s_at[t] = make_float4(0.f, 0.f, 0.f, 1e30f);  // never a hit
            }
        }
        __syncthreads();
    }

    int lane = threadIdx.x & 31;
    int wid  = (threadIdx.x >> 5) + blockIdx.y * (blockDim.x >> 5);
    int wtot = (blockDim.x >> 5) * gridDim.y;

    for (int base = 0; base * wtot < ngroups; base++) {
        int g = (base & 1) ? ((base + 1) * wtot - 1 - wid) : (base * wtot + wid);
        if (g >= ngroups) continue;

        int r0 = g * IT;
        // Load 4 rows, un-double (+exact), negate xyz (exact), keep sq.
        float nx[IT], ny[IT], nz[IT], w[IT];
#pragma unroll
        for (int t = 0; t < IT; t++) {
            int i = r0 + t;
            if (i < nat) {
                float4 v = s_at[i];
                nx[t] = -0.5f * v.x; ny[t] = -0.5f * v.y; nz[t] = -0.5f * v.z;
                w[t] = v.w;
            } else {
                nx[t] = 0.f; ny[t] = 0.f; nz[t] = 0.f; w[t] = 1e30f;
            }
        }
        u64 nax01 = pack2(nx[0], nx[1]), nay01 = pack2(ny[0], ny[1]);
        u64 naz01 = pack2(nz[0], nz[1]), aw01  = pack2(w[0],  w[1]);
        u64 nax23 = pack2(nx[2], nx[3]), nay23 = pack2(ny[2], ny[3]);
        u64 naz23 = pack2(nz[2], nz[3]), aw23  = pack2(w[2],  w[3]);

        uint4* mp = &g_mask[(size_t)(s * ngroups + g) * nch];
        int c0 = (r0 + 1) >> 5;
        int cnt0 = 0, cnt1 = 0, cnt2 = 0, cnt3 = 0;

        // Peeled first chunk: needs the j > i predicate.
        int c = c0;
        if (c < nch) {
            int j = (c << 5) + lane;
            float4 aj = s_at[j];
            u64 jx = pack2(aj.x, aj.x), jy = pack2(aj.y, aj.y);
            u64 jz = pack2(aj.z, aj.z), jw = pack2(aj.w, aj.w);
            float d0, d1, d2, d3;
            unpack2(d12_pair(nax01, nay01, naz01, aw01, jx, jy, jz, jw), d0, d1);
            unpack2(d12_pair(nax23, nay23, naz23, aw23, jx, jy, jz, jw), d2, d3);
            unsigned m0 = __ballot_sync(0xffffffffu, (d0 < CUT2) && (j > r0));
            unsigned m1 = __ballot_sync(0xffffffffu, (d1 < CUT2) && (j > r0 + 1));
            unsigned m2 = __ballot_sync(0xffffffffu, (d2 < CUT2) && (j > r0 + 2));
            unsigned m3 = __ballot_sync(0xffffffffu, (d3 < CUT2) && (j > r0 + 3));
            if (lane == 0) mp[c] = make_uint4(m0, m1, m2, m3);
            cnt0 += __popc(m0); cnt1 += __popc(m1);
            cnt2 += __popc(m2); cnt3 += __popc(m3);
            c++;
        }

        // Clean chunks: j > i guaranteed; sentinels kill j >= nat.
        for (; c < nch; c++) {
            int j = (c << 5) + lane;
            float4 aj = s_at[j];
            u64 jx = pack2(aj.x, aj.x), jy = pack2(aj.y, aj.y);
            u64 jz = pack2(aj.z, aj.z), jw = pack2(aj.w, aj.w);
            float d0, d1, d2, d3;
            unpack2(d12_pair(nax01, nay01, naz01, aw01, jx, jy, jz, jw), d0, d1);
            unpack2(d12_pair(nax23, nay23, naz23, aw23, jx, jy, jz, jw), d2, d3);
            unsigned m0 = __ballot_sync(0xffffffffu, d0 < CUT2);
            unsigned m1 = __ballot_sync(0xffffffffu, d1 < CUT2);
            unsigned m2 = __ballot_sync(0xffffffffu, d2 < CUT2);
            unsigned m3 = __ballot_sync(0xffffffffu, d3 < CUT2);
            if (lane == 0) mp[c] = make_uint4(m0, m1, m2, m3);
            cnt0 += __popc(m0); cnt1 += __popc(m1);
            cnt2 += __popc(m2); cnt3 += __popc(m3);
        }

        if (lane == 0)
            g_counts4[s * ngroups + g] = make_int4(cnt0, cnt1, cnt2, cnt3);
    }
}

// K2: per-system exclusive scan over per-row counts (coalesced int loads).
__global__ void scan_sys_kernel(int nat, int ngroups) {
    __shared__ int wsum[32];
    int s = blockIdx.x;
    int tid = threadIdx.x;
    int lane = tid & 31, w = tid >> 5;

    const int* cnts = (const int*)&g_counts4[(size_t)s * ngroups];
    int v = (tid < nat) ? cnts[tid] : 0;

    int x = v;
#pragma unroll
    for (int o = 1; o < 32; o <<= 1) {
        int u = __shfl_up_sync(0xffffffffu, x, o);
        if (lane >= o) x += u;
    }
    if (lane == 31) wsum[w] = x;
    __syncthreads();
    if (w == 0) {
        int y = wsum[lane];
#pragma unroll
        for (int o = 1; o < 32; o <<= 1) {
            int u = __shfl_up_sync(0xffffffffu, y, o);
            if (lane >= o) y += u;
        }
        wsum[lane] = y;
    }
    __syncthreads();
    int incl = x + ((w > 0) ? wsum[w - 1] : 0);
    if (tid < nat) g_offsets[s * nat + tid] = incl - v;
    if (tid == nat - 1) g_systot[s] = incl;
}

// K3: fused output, hit-parallel. Blocks [0, WB): one warp per row; lane c
// loads chunk c's mask; shfl-scan gives per-chunk bases; then lane k handles
// the k-th hit of the row (shfl binary search + __fns bit extract), so stores
// are fully coalesced and each lane has ONE independent LDG chain.
// Blocks [WB, ...): padding region (concurrent, disjoint).
// Output float32 layout (maxp = MAX_PAIRS):
//   [0,M): src   [M,2M): dst    (edge_src = concat(src,dst))
//   [2M,3M): dst [3M,4M): src   (edge_dst = concat(dst,src))
//   [4M,5M): d12 [5M,6M): d12   [6M]: npairs
__global__ void output_kernel(const float* __restrict__ coords,
                              float* __restrict__ out, int maxp, int nrows,
                              int nat, int nsys, int nch, int ngroups,
                              int WB, float padval, int vec_ok) {
    __shared__ int s_sysoff[NSYS_SM];
    int tid = threadIdx.x;
    if (tid < 32) {
        int per = (nsys + 31) >> 5;
        int bbase = tid * per;
        int loc[8];
        int sum = 0;
        for (int u = 0; u < per && u < 8; u++) {
            int idx = bbase + u;
            int t = (idx < nsys) ? g_systot[idx] : 0;
            loc[u] = sum;
            sum += t;
        }
        int x = sum;
#pragma unroll
        for (int o = 1; o < 32; o <<= 1) {
            int uu = __shfl_up_sync(0xffffffffu, x, o);
            if (tid >= o) x += uu;
        }
        int excl = x - sum;
        for (int u = 0; u < per && u < 8; u++) {
            int idx = bbase + u;
            if (idx < nsys && idx < NSYS_SM) s_sysoff[idx] = excl + loc[u];
        }
        if (tid == 31 && nsys < NSYS_SM) s_sysoff[nsys] = x;  // npairs
    }
    __syncthreads();
    int np = s_sysoff[nsys];

    if (blockIdx.x < WB) {
        int row = blockIdx.x * (blockDim.x >> 5) + (tid >> 5);
        if (row >= nrows) return;              // warp-uniform
        int lane = tid & 31;
        int s = row / nat, i = row - s * nat;
        int g = i >> 2, t = i & 3;
        int c0 = ((g << 2) + 1) >> 5;

        unsigned m = 0;
        if (lane >= c0 && lane < nch)
            m = ((const unsigned*)&g_mask[(size_t)(s * ngroups + g) * nch])
                 [(lane << 2) + t];
        int cnt = __popc(m);

        int x = cnt;  // inclusive scan across lanes (chunks)
#pragma unroll
        for (int o = 1; o < 32; o <<= 1) {
            int u = __shfl_up_sync(0xffffffffu, x, o);
            if (lane >= o) x += u;
        }
        int mybase = x - cnt;                       // non-decreasing over lanes
        int total = __shfl_sync(0xffffffffu, x, 31);
        if (total == 0) return;                     // warp-uniform

        const float* ci = coords + (size_t)row * 3;
        float xi = __ldg(ci), yi = __ldg(ci + 1), zi = __ldg(ci + 2);
        float4 ai = make_float4(xi, yi, zi, sqnorm3(xi, yi, zi));
        float fsrc = (float)row;
        float fsysbase = (float)(s * nat);
        int off = s_sysoff[s] + g_offsets[row];
        int sysbase = s * nat;

        for (int kb = 0; kb < total; kb += 32) {   // all lanes iterate together
            int k = kb + lane;
            // binary search: largest lane c with mybase[c] <= k
            int c = 0;
#pragma unroll
            for (int st = 16; st; st >>= 1) {
                int tt = c + st;
                int bt = __shfl_sync(0xffffffffu, mybase, tt & 31);
                if (tt < 32 && bt <= k) c = tt;
            }
            unsigned mc = __shfl_sync(0xffffffffu, m, c);
            int bc = __shfl_sync(0xffffffffu, mybase, c);
            if (k < total) {
                int r = k - bc;
                int bit = __fns(mc, 0, r + 1);      // (r+1)-th set bit from 0
                int j = (c << 5) + bit;
                const float* cj = coords + (size_t)(sysbase + j) * 3;
                float xj = __ldg(cj), yj = __ldg(cj + 1), zj = __ldg(cj + 2);
                float4 aj = make_float4(xj, yj, zj, sqnorm3(xj, yj, zj));
                float d = d12_of(ai, aj);
                int pos = off + k;
                if (pos < maxp) {
                    float fdst = fsysbase + (float)j;
                    out[pos]            = fsrc;
                    out[maxp + pos]     = fdst;
                    out[2 * maxp + pos] = fdst;
                    out[3 * maxp + pos] = fsrc;
                    out[4 * maxp + pos] = d;
                    out[5 * maxp + pos] = d;
                }
            }
        }
    } else {
        int pb = blockIdx.x - WB;
        if (pb == 0 && tid == 0) out[6 * maxp] = (float)np;
        int k0 = (pb * blockDim.x + tid) * 4;
        if (k0 >= maxp) return;
        if (k0 >= np && k0 + 3 < maxp && vec_ok) {
            float4 pv = make_float4(padval, padval, padval, padval);
            float4 cv = make_float4(CUT2, CUT2, CUT2, CUT2);
            *(float4*)(out + k0)            = pv;
            *(float4*)(out + maxp + k0)     = pv;
            *(float4*)(out + 2 * maxp + k0) = pv;
            *(float4*)(out + 3 * maxp + k0) = pv;
            *(float4*)(out + 4 * maxp + k0) = cv;
            *(float4*)(out + 5 * maxp + k0) = cv;
        } else {
#pragma unroll
            for (int u = 0; u < 4; u++) {
                int k = k0 + u;
                if (k < maxp && k >= np) {
                    out[k]            = padval;
                    out[maxp + k]     = padval;
                    out[2 * maxp + k] = padval;
                    out[3 * maxp + k] = padval;
                    out[4 * maxp + k] = CUT2;
                    out[5 * maxp + k] = CUT2;
                }
            }
        }
    }
}

extern "C" void kernel_launch(void* const* d_in, const int* in_sizes, int n_in,
                              void* d_out, int out_size) {
    const float* coords = (const float*)d_in[0];
    int n    = in_sizes[1];          // total atoms
    int nsys = in_sizes[2];          // systems
    int nat  = n / nsys;
    int maxp = (out_size - 1) / 6;   // MAX_PAIRS
    float* out = (float*)d_out;

    int nch = (nat + 31) >> 5;            // 32-wide j-chunks per row (<= 32)
    int ngroups = (nat + IT - 1) / IT;
    size_t smem_sweep = (size_t)nch * 32 * sizeof(float4);
    int vec_ok = ((maxp & 3) == 0) ? 1 : 0;

    int WB = (n + 7) / 8;                          // write blocks (8 warps ea)
    int PB = (maxp + 256 * 4 - 1) / (256 * 4);     // pad blocks

    sweep_kernel<<<dim3(nsys, 16), 256, smem_sweep>>>(coords, nat, nch, ngroups);
    scan_sys_kernel<<<nsys, 1024>>>(nat, ngroups);
    output_kernel<<<WB + PB, 256>>>(coords, out, maxp, n, nat, nsys, nch,
                                    ngroups, WB, (float)n, vec_ok);
}